// round 4
// baseline (speedup 1.0000x reference)
#include <cuda_runtime.h>
#include <math.h>

// Problem dims
#define B_   64
#define NI   2048
#define DI   16
#define NO   32
#define DO_  32
#define OD   1024        // NO * DO_
#define EPSQ 1e-7f

// Scratch (device globals; no allocation in kernel_launch)
__device__ float g_uhat[(size_t)B_ * NI * OD];   // [b][i][o*32+d]  (512 MB)
__device__ float g_spart[(size_t)B_ * 16 * OD];  // per-(b,chunk) partial s  (4 MB)
__device__ float g_vsum[B_ * OD];                // cumulative sum of v over iterations

// ---------------------------------------------------------------------------
__global__ void k_zero_vsum() {
    int t = blockIdx.x * blockDim.x + threadIdx.x;   // 64*256 = 16384 float4
    ((float4*)g_vsum)[t] = make_float4(0.f, 0.f, 0.f, 0.f);
}

// ---------------------------------------------------------------------------
// u_hat[b,i,o,d] = sum_k W[o,i,d,k] * x[b,i,k]
// grid (2048, 2): blockIdx.x = i, blockIdx.y = o-half (16 o's).  128 threads.
#define WPITCH 520      // 512 + 8 pad (float), keeps float4 alignment (520*4 % 16 == 0)
__global__ __launch_bounds__(128) void k_transform(const float* __restrict__ x,
                                                   const float* __restrict__ W) {
    __shared__ float Ws[16 * WPITCH];   // [k][o_local*32+d]
    __shared__ float xs[16 * 64];       // [k][b]
    const int i   = blockIdx.x;
    const int oc  = blockIdx.y;         // 0 or 1
    const int tid = threadIdx.x;

    // Stage W[:, i, :, :] for 16 o's: W[o][i][d][k], (d,k) block is 512 contiguous floats
    for (int l = tid; l < 16 * 512; l += 128) {
        int ol = l >> 9;                 // local o  0..15
        int dk = l & 511;
        int d  = dk >> 4;
        int k  = dk & 15;
        Ws[k * WPITCH + ol * 32 + d] =
            W[(((size_t)(oc * 16 + ol)) * NI + i) * 512 + dk];
    }
    // Stage x[:, i, :]
    for (int l = tid; l < 64 * 16; l += 128) {
        int b = l >> 4;
        int k = l & 15;
        xs[k * 64 + b] = x[((size_t)b * NI + i) * 16 + k];
    }
    __syncthreads();

    const int od0 = tid * 4;            // 128 threads * 4 = 512 od per o-half
    for (int b0 = 0; b0 < 64; b0 += 8) {
        float acc[8][4];
        #pragma unroll
        for (int bb = 0; bb < 8; bb++) {
            acc[bb][0] = acc[bb][1] = acc[bb][2] = acc[bb][3] = 0.f;
        }
        #pragma unroll
        for (int k = 0; k < 16; k++) {
            float4 w  = *(const float4*)&Ws[k * WPITCH + od0];
            float4 xa = *(const float4*)&xs[k * 64 + b0];
            float4 xb = *(const float4*)&xs[k * 64 + b0 + 4];
            float xv[8] = {xa.x, xa.y, xa.z, xa.w, xb.x, xb.y, xb.z, xb.w};
            #pragma unroll
            for (int bb = 0; bb < 8; bb++) {
                acc[bb][0] = fmaf(xv[bb], w.x, acc[bb][0]);
                acc[bb][1] = fmaf(xv[bb], w.y, acc[bb][1]);
                acc[bb][2] = fmaf(xv[bb], w.z, acc[bb][2]);
                acc[bb][3] = fmaf(xv[bb], w.w, acc[bb][3]);
            }
        }
        #pragma unroll
        for (int bb = 0; bb < 8; bb++) {
            size_t base = (((size_t)(b0 + bb)) * NI + i) * OD + oc * 512 + od0;
            *(float4*)&g_uhat[base] =
                make_float4(acc[bb][0], acc[bb][1], acc[bb][2], acc[bb][3]);
        }
    }
}

// ---------------------------------------------------------------------------
// One fused routing pass: per (b,i): bb[o] = vsum[b,o,:]·u_hat[b,i,o,:],
// c = softmax_o(bb), s_partial[b,o,d] += c[o]*u_hat.  Deterministic partials.
// grid 1024: blockIdx.x = b*16 + chunk (chunk = 128 i's). 256 threads = 8 warps,
// each warp owns 4 consecutive o's, lane = d.
__global__ __launch_bounds__(256) void k_route() {
    __shared__ float bb_s[32];
    const int c    = blockIdx.x;
    const int b    = c >> 4;
    const int i0   = (c & 15) * 128;
    const int w    = threadIdx.x >> 5;
    const int lane = threadIdx.x & 31;

    float vs[4], sacc[4];
    #pragma unroll
    for (int j = 0; j < 4; j++) {
        vs[j]   = g_vsum[b * OD + (w * 4 + j) * 32 + lane];
        sacc[j] = 0.f;
    }
    const float* up = g_uhat + ((size_t)b * NI + i0) * OD;

    for (int ii = 0; ii < 128; ii++) {
        float u[4];
        #pragma unroll
        for (int j = 0; j < 4; j++)
            u[j] = up[(size_t)ii * OD + (w * 4 + j) * 32 + lane];

        // bb[o] = sum_d vs*u  (warp allreduce over lanes)
        float p[4];
        #pragma unroll
        for (int j = 0; j < 4; j++) {
            float v = vs[j] * u[j];
            #pragma unroll
            for (int s = 16; s > 0; s >>= 1)
                v += __shfl_xor_sync(0xffffffffu, v, s);
            p[j] = v;
        }
        if (lane == 0) {
            #pragma unroll
            for (int j = 0; j < 4; j++) bb_s[w * 4 + j] = p[j];
        }
        __syncthreads();

        // softmax over the 32 output capsules (each warp computes it redundantly)
        float e = bb_s[lane];
        float m = e;
        #pragma unroll
        for (int s = 16; s > 0; s >>= 1)
            m = fmaxf(m, __shfl_xor_sync(0xffffffffu, m, s));
        float ex = expf(e - m);
        float sum = ex;
        #pragma unroll
        for (int s = 16; s > 0; s >>= 1)
            sum += __shfl_xor_sync(0xffffffffu, sum, s);
        float inv = 1.f / sum;

        #pragma unroll
        for (int j = 0; j < 4; j++) {
            float cj = __shfl_sync(0xffffffffu, ex, w * 4 + j) * inv;
            sacc[j] = fmaf(cj, u[j], sacc[j]);
        }
        __syncthreads();   // protect bb_s before next iteration
    }

    #pragma unroll
    for (int j = 0; j < 4; j++)
        g_spart[(size_t)c * OD + (w * 4 + j) * 32 + lane] = sacc[j];
}

// ---------------------------------------------------------------------------
// Reduce the 16 deterministic partials, squash, update vsum (or emit output).
// 2048 (b,o) warps -> grid 256 x 256 threads.
__global__ __launch_bounds__(256) void k_squash(float* __restrict__ out, int final_) {
    const int g    = blockIdx.x * 8 + (threadIdx.x >> 5);
    const int lane = threadIdx.x & 31;
    const int b    = g >> 5;
    const int o    = g & 31;

    float val = 0.f;
    #pragma unroll
    for (int j = 0; j < 16; j++)
        val += g_spart[((size_t)(b * 16 + j)) * OD + o * 32 + lane];

    float sq = val * val;
    #pragma unroll
    for (int s = 16; s > 0; s >>= 1)
        sq += __shfl_xor_sync(0xffffffffu, sq, s);

    float scale = sq / (1.f + sq) / sqrtf(sq + EPSQ);
    float v = val * scale;

    if (final_)
        out[((size_t)b * 32 + o) * 32 + lane] = v;
    else
        g_vsum[b * OD + o * 32 + lane] += v;
}

// ---------------------------------------------------------------------------
extern "C" void kernel_launch(void* const* d_in, const int* in_sizes, int n_in,
                              void* d_out, int out_size) {
    const float* x = (const float*)d_in[0];   // [64, 2048, 16]
    const float* W = (const float*)d_in[1];   // [32, 2048, 32, 16]
    float* out = (float*)d_out;               // [64, 32, 32]

    k_zero_vsum<<<64, 256>>>();
    k_transform<<<dim3(NI, 2), 128>>>(x, W);
    for (int r = 0; r < 3; r++) {
        k_route<<<B_ * 16, 256>>>();
        k_squash<<<256, 256>>>(out, (r == 2) ? 1 : 0);
    }
}

// round 9
// speedup vs baseline: 1.6521x; 1.6521x over previous
#include <cuda_runtime.h>
#include <math.h>

// Problem dims
#define B_   64
#define NI   2048
#define DI   16
#define NO   32
#define DO_  32
#define OD   1024        // NO * DO_
#define EPSQ 1e-7f

// Scratch (device globals; no allocation in kernel_launch)
__device__ float g_uhat[(size_t)B_ * NI * OD];   // [b][i][o*32+d]  (512 MB)
__device__ float g_spart[(size_t)B_ * 8 * OD];   // per-(b,chunk) partial s
__device__ float g_vsum[B_ * OD];                // cumulative sum of v over iterations

// ---------------------------------------------------------------------------
__global__ void k_zero_vsum() {
    int t = blockIdx.x * blockDim.x + threadIdx.x;   // 64*256 = 16384 float4
    ((float4*)g_vsum)[t] = make_float4(0.f, 0.f, 0.f, 0.f);
}

// ---------------------------------------------------------------------------
// u_hat[b,i,o,d] = sum_k W[o,i,d,k] * x[b,i,k]
// grid (2048, 2): blockIdx.x = i, blockIdx.y = o-half (16 o's).  128 threads.
#define WPITCH 520      // 512 + 8 pad (float), keeps float4 alignment
__global__ __launch_bounds__(128) void k_transform(const float* __restrict__ x,
                                                   const float* __restrict__ W) {
    __shared__ float Ws[16 * WPITCH];   // [k][o_local*32+d]
    __shared__ float xs[16 * 64];       // [k][b]
    const int i   = blockIdx.x;
    const int oc  = blockIdx.y;         // 0 or 1
    const int tid = threadIdx.x;

    for (int l = tid; l < 16 * 512; l += 128) {
        int ol = l >> 9;
        int dk = l & 511;
        int d  = dk >> 4;
        int k  = dk & 15;
        Ws[k * WPITCH + ol * 32 + d] =
            W[(((size_t)(oc * 16 + ol)) * NI + i) * 512 + dk];
    }
    for (int l = tid; l < 64 * 16; l += 128) {
        int b = l >> 4;
        int k = l & 15;
        xs[k * 64 + b] = x[((size_t)b * NI + i) * 16 + k];
    }
    __syncthreads();

    const int od0 = tid * 4;
    for (int b0 = 0; b0 < 64; b0 += 8) {
        float acc[8][4];
        #pragma unroll
        for (int bb = 0; bb < 8; bb++)
            acc[bb][0] = acc[bb][1] = acc[bb][2] = acc[bb][3] = 0.f;
        #pragma unroll
        for (int k = 0; k < 16; k++) {
            float4 w  = *(const float4*)&Ws[k * WPITCH + od0];
            float4 xa = *(const float4*)&xs[k * 64 + b0];
            float4 xb = *(const float4*)&xs[k * 64 + b0 + 4];
            float xv[8] = {xa.x, xa.y, xa.z, xa.w, xb.x, xb.y, xb.z, xb.w};
            #pragma unroll
            for (int bb = 0; bb < 8; bb++) {
                acc[bb][0] = fmaf(xv[bb], w.x, acc[bb][0]);
                acc[bb][1] = fmaf(xv[bb], w.y, acc[bb][1]);
                acc[bb][2] = fmaf(xv[bb], w.z, acc[bb][2]);
                acc[bb][3] = fmaf(xv[bb], w.w, acc[bb][3]);
            }
        }
        #pragma unroll
        for (int bb = 0; bb < 8; bb++) {
            size_t base = (((size_t)(b0 + bb)) * NI + i) * OD + oc * 512 + od0;
            *(float4*)&g_uhat[base] =
                make_float4(acc[bb][0], acc[bb][1], acc[bb][2], acc[bb][3]);
        }
    }
}

// ---------------------------------------------------------------------------
// Iteration 0: softmax of zero logits is exactly uniform (c = 1/32), so
// s0[b,od] = (1/32) * sum_i u_hat[b,i,od].  Pure streaming reduction.
// grid 512: blockIdx.x = b*8 + chunk (chunk = 256 i's). 256 threads.
__global__ __launch_bounds__(256) void k_sum0() {
    const int b     = blockIdx.x >> 3;
    const int chunk = blockIdx.x & 7;
    const float4* up = (const float4*)(g_uhat + ((size_t)b * NI + chunk * 256) * OD)
                       + threadIdx.x;
    float4 a0 = make_float4(0.f, 0.f, 0.f, 0.f);
    float4 a1 = make_float4(0.f, 0.f, 0.f, 0.f);
    #pragma unroll 4
    for (int ii = 0; ii < 256; ii += 2) {
        float4 v0 = up[(size_t)ii * 256];
        float4 v1 = up[(size_t)(ii + 1) * 256];
        a0.x += v0.x; a0.y += v0.y; a0.z += v0.z; a0.w += v0.w;
        a1.x += v1.x; a1.y += v1.y; a1.z += v1.z; a1.w += v1.w;
    }
    const float sc = 1.f / 32.f;
    float4 r = make_float4((a0.x + a1.x) * sc, (a0.y + a1.y) * sc,
                           (a0.z + a1.z) * sc, (a0.w + a1.w) * sc);
    ((float4*)(g_spart + ((size_t)blockIdx.x) * OD))[threadIdx.x] = r;
}

// ---------------------------------------------------------------------------
// Routing pass (iterations 1,2), lane = output capsule o.
// Each lane loads the contiguous 128B row u[o,0:32] (8x float4; the warp's 32
// lanes cover the whole 4KB i-row, fully coalesced). bb[o] = vsum[o,:]·u[o,:]
// is a per-lane FMA chain (NO cross-lane reduce). Softmax over o = 2 warp
// reductions. s accumulators are register-resident. No barriers in the loop.
// grid 512: blockIdx.x = b*8 + chunk (256 i's); 8 warps x 32 i's each.
__global__ __launch_bounds__(256) void k_route() {
    __shared__ float red[8 * 32 * 33];
    const int b     = blockIdx.x >> 3;
    const int chunk = blockIdx.x & 7;
    const int w     = threadIdx.x >> 5;
    const int o     = threadIdx.x & 31;

    float vs[32];
    const float* vp = g_vsum + b * OD + o * 32;
    #pragma unroll
    for (int d = 0; d < 32; d++) vs[d] = vp[d];

    float sacc[32];
    #pragma unroll
    for (int d = 0; d < 32; d++) sacc[d] = 0.f;

    const float4* up = (const float4*)(g_uhat
        + ((size_t)b * NI + chunk * 256 + w * 32) * OD + o * 32);
    // successive i: stride OD/4 = 256 float4

    float4 cur[8], nxt[8];
    #pragma unroll
    for (int j = 0; j < 8; j++) cur[j] = up[j];

    for (int ii = 0; ii < 32; ii++) {
        if (ii < 31) {
            const float4* un = up + (size_t)(ii + 1) * 256;
            #pragma unroll
            for (int j = 0; j < 8; j++) nxt[j] = un[j];
        }
        // bb[o] = sum_d vs[d]*u[d]  (4 independent FMA chains)
        float d0 = 0.f, d1 = 0.f, d2 = 0.f, d3 = 0.f;
        #pragma unroll
        for (int j = 0; j < 8; j++) {
            d0 = fmaf(vs[4 * j + 0], cur[j].x, d0);
            d1 = fmaf(vs[4 * j + 1], cur[j].y, d1);
            d2 = fmaf(vs[4 * j + 2], cur[j].z, d2);
            d3 = fmaf(vs[4 * j + 3], cur[j].w, d3);
        }
        float bb = (d0 + d1) + (d2 + d3);

        // softmax over the 32 lanes (= 32 output capsules)
        float m = bb;
        #pragma unroll
        for (int s = 16; s > 0; s >>= 1)
            m = fmaxf(m, __shfl_xor_sync(0xffffffffu, m, s));
        float ex = expf(bb - m);
        float sum = ex;
        #pragma unroll
        for (int s = 16; s > 0; s >>= 1)
            sum += __shfl_xor_sync(0xffffffffu, sum, s);
        float c = ex / sum;

        #pragma unroll
        for (int j = 0; j < 8; j++) {
            sacc[4 * j + 0] = fmaf(c, cur[j].x, sacc[4 * j + 0]);
            sacc[4 * j + 1] = fmaf(c, cur[j].y, sacc[4 * j + 1]);
            sacc[4 * j + 2] = fmaf(c, cur[j].z, sacc[4 * j + 2]);
            sacc[4 * j + 3] = fmaf(c, cur[j].w, sacc[4 * j + 3]);
        }
        #pragma unroll
        for (int j = 0; j < 8; j++) cur[j] = nxt[j];
    }

    // block reduce the 8 warps' register partials (pitch 33 -> conflict-free)
    float* rp = red + (w * 32 + o) * 33;
    #pragma unroll
    for (int d = 0; d < 32; d++) rp[d] = sacc[d];
    __syncthreads();

    const int od0 = threadIdx.x * 4;
    float r[4] = {0.f, 0.f, 0.f, 0.f};
    #pragma unroll
    for (int w2 = 0; w2 < 8; w2++) {
        #pragma unroll
        for (int q = 0; q < 4; q++) {
            int od = od0 + q;
            r[q] += red[(w2 * 32 + (od >> 5)) * 33 + (od & 31)];
        }
    }
    *(float4*)&g_spart[((size_t)blockIdx.x) * OD + od0] =
        make_float4(r[0], r[1], r[2], r[3]);
}

// ---------------------------------------------------------------------------
// Reduce the 8 deterministic partials, squash, update vsum (or emit output).
__global__ __launch_bounds__(256) void k_squash(float* __restrict__ out, int final_) {
    const int g    = blockIdx.x * 8 + (threadIdx.x >> 5);
    const int lane = threadIdx.x & 31;
    const int b    = g >> 5;
    const int o    = g & 31;

    float val = 0.f;
    #pragma unroll
    for (int j = 0; j < 8; j++)
        val += g_spart[((size_t)(b * 8 + j)) * OD + o * 32 + lane];

    float sq = val * val;
    #pragma unroll
    for (int s = 16; s > 0; s >>= 1)
        sq += __shfl_xor_sync(0xffffffffu, sq, s);

    float scale = sq / (1.f + sq) / sqrtf(sq + EPSQ);
    float v = val * scale;

    if (final_)
        out[((size_t)b * 32 + o) * 32 + lane] = v;
    else
        g_vsum[b * OD + o * 32 + lane] += v;
}

// ---------------------------------------------------------------------------
extern "C" void kernel_launch(void* const* d_in, const int* in_sizes, int n_in,
                              void* d_out, int out_size) {
    const float* x = (const float*)d_in[0];   // [64, 2048, 16]
    const float* W = (const float*)d_in[1];   // [32, 2048, 32, 16]
    float* out = (float*)d_out;               // [64, 32, 32]

    k_zero_vsum<<<64, 256>>>();
    k_transform<<<dim3(NI, 2), 128>>>(x, W);

    // iteration 0: uniform coupling (softmax of zeros) -> plain mean
    k_sum0<<<B_ * 8, 256>>>();
    k_squash<<<256, 256>>>(out, 0);

    // iterations 1,2
    k_route<<<B_ * 8, 256>>>();
    k_squash<<<256, 256>>>(out, 0);
    k_route<<<B_ * 8, 256>>>();
    k_squash<<<256, 256>>>(out, 1);
}

// round 14
// speedup vs baseline: 2.6722x; 1.6175x over previous
#include <cuda_runtime.h>
#include <cuda_fp16.h>
#include <math.h>

// Problem dims
#define B_   64
#define NI   2048
#define DI   16
#define NO   32
#define DO_  32
#define OD   1024        // NO * DO_
#define EPSQ 1e-7f

// Scratch (device globals; no allocation in kernel_launch)
// u_hat stored as fp16: [b][i][o*32+d], 268 MB. Declared as uint4 for 16B align.
__device__ uint4  g_uhat[(size_t)B_ * NI * OD / 8];
__device__ float  g_spart[(size_t)B_ * 8 * OD];   // per-(b,chunk) partial s
__device__ float  g_vsum[B_ * OD];                // cumulative sum of v

// ---------------------------------------------------------------------------
__global__ void k_zero_vsum() {
    int t = blockIdx.x * blockDim.x + threadIdx.x;   // 64*256 = 16384 float4
    ((float4*)g_vsum)[t] = make_float4(0.f, 0.f, 0.f, 0.f);
}

// ---------------------------------------------------------------------------
// u_hat[b,i,o,d] = sum_k W[o,i,d,k] * x[b,i,k]   (fp32 math, fp16 store)
// grid (2048, 2): blockIdx.x = i, blockIdx.y = o-half (16 o's).  128 threads.
#define WPITCH 520      // 512 + 8 pad (float), keeps float4 alignment
__global__ __launch_bounds__(128) void k_transform(const float* __restrict__ x,
                                                   const float* __restrict__ W) {
    __shared__ float Ws[16 * WPITCH];   // [k][o_local*32+d]
    __shared__ float xs[16 * 64];       // [k][b]
    const int i   = blockIdx.x;
    const int oc  = blockIdx.y;         // 0 or 1
    const int tid = threadIdx.x;

    for (int l = tid; l < 16 * 512; l += 128) {
        int ol = l >> 9;
        int dk = l & 511;
        int d  = dk >> 4;
        int k  = dk & 15;
        Ws[k * WPITCH + ol * 32 + d] =
            W[(((size_t)(oc * 16 + ol)) * NI + i) * 512 + dk];
    }
    for (int l = tid; l < 64 * 16; l += 128) {
        int b = l >> 4;
        int k = l & 15;
        xs[k * 64 + b] = x[((size_t)b * NI + i) * 16 + k];
    }
    __syncthreads();

    uint2* uout = (uint2*)g_uhat;       // 1 uint2 = 4 halves
    const int od0 = tid * 4;
    for (int b0 = 0; b0 < 64; b0 += 8) {
        float acc[8][4];
        #pragma unroll
        for (int bb = 0; bb < 8; bb++)
            acc[bb][0] = acc[bb][1] = acc[bb][2] = acc[bb][3] = 0.f;
        #pragma unroll
        for (int k = 0; k < 16; k++) {
            float4 w  = *(const float4*)&Ws[k * WPITCH + od0];
            float4 xa = *(const float4*)&xs[k * 64 + b0];
            float4 xb = *(const float4*)&xs[k * 64 + b0 + 4];
            float xv[8] = {xa.x, xa.y, xa.z, xa.w, xb.x, xb.y, xb.z, xb.w};
            #pragma unroll
            for (int bb = 0; bb < 8; bb++) {
                acc[bb][0] = fmaf(xv[bb], w.x, acc[bb][0]);
                acc[bb][1] = fmaf(xv[bb], w.y, acc[bb][1]);
                acc[bb][2] = fmaf(xv[bb], w.z, acc[bb][2]);
                acc[bb][3] = fmaf(xv[bb], w.w, acc[bb][3]);
            }
        }
        #pragma unroll
        for (int bb = 0; bb < 8; bb++) {
            size_t base = (((size_t)(b0 + bb)) * NI + i) * OD + oc * 512 + od0;
            __half2 h01 = __floats2half2_rn(acc[bb][0], acc[bb][1]);
            __half2 h23 = __floats2half2_rn(acc[bb][2], acc[bb][3]);
            uint2 pk;
            pk.x = *(const unsigned*)&h01;
            pk.y = *(const unsigned*)&h23;
            uout[base >> 2] = pk;
        }
    }
}

// ---------------------------------------------------------------------------
// Iteration 0: softmax of zero logits is exactly uniform (c = 1/32), so
// s0[b,od] = (1/32) * sum_i u_hat[b,i,od].  Pure streaming reduction.
// grid 512: blockIdx.x = b*8 + chunk (chunk = 256 i's). 256 threads, 4 od each.
__global__ __launch_bounds__(256) void k_sum0() {
    const int b     = blockIdx.x >> 3;
    const int chunk = blockIdx.x & 7;
    const uint2* up = (const uint2*)g_uhat
        + ((size_t)b * NI + chunk * 256) * (OD / 4) + threadIdx.x;
    float a0 = 0.f, a1 = 0.f, a2 = 0.f, a3 = 0.f;
    #pragma unroll 4
    for (int ii = 0; ii < 256; ii++) {
        uint2 v = up[(size_t)ii * 256];
        float2 f01 = __half22float2(*(const __half2*)&v.x);
        float2 f23 = __half22float2(*(const __half2*)&v.y);
        a0 += f01.x; a1 += f01.y; a2 += f23.x; a3 += f23.y;
    }
    const float sc = 1.f / 32.f;
    *(float4*)&g_spart[((size_t)blockIdx.x) * OD + threadIdx.x * 4] =
        make_float4(a0 * sc, a1 * sc, a2 * sc, a3 * sc);
}

// ---------------------------------------------------------------------------
// Routing pass (iterations 1,2), lane = output capsule o.
// Lane loads the contiguous 64B fp16 row u[o,0:32] (4x uint4; warp covers the
// whole 2KB i-row coalesced). bb[o] = vsum[o,:]·u[o,:] is per-lane FMAs (no
// cross-lane reduce); softmax over o = 2 warp reductions; s accumulators in
// registers; no barriers in the loop.
// grid 512: blockIdx.x = b*8 + chunk (256 i's); 8 warps x 32 i's each.
__global__ __launch_bounds__(256) void k_route() {
    __shared__ float red[8 * 32 * 33];
    const int b     = blockIdx.x >> 3;
    const int chunk = blockIdx.x & 7;
    const int w     = threadIdx.x >> 5;
    const int o     = threadIdx.x & 31;

    float vs[32];
    const float* vp = g_vsum + b * OD + o * 32;
    #pragma unroll
    for (int d = 0; d < 32; d++) vs[d] = vp[d];

    float sacc[32];
    #pragma unroll
    for (int d = 0; d < 32; d++) sacc[d] = 0.f;

    const uint4* up = (const uint4*)g_uhat
        + ((size_t)b * NI + chunk * 256 + w * 32) * (OD / 8) + o * 4;
    // successive i: stride OD/8 = 128 uint4

    uint4 cur[4], nxt[4];
    #pragma unroll
    for (int j = 0; j < 4; j++) cur[j] = up[j];

    for (int ii = 0; ii < 32; ii++) {
        if (ii < 31) {
            const uint4* un = up + (size_t)(ii + 1) * 128;
            #pragma unroll
            for (int j = 0; j < 4; j++) nxt[j] = un[j];
        }
        // unpack 32 halves -> fp32
        float u[32];
        #pragma unroll
        for (int j = 0; j < 4; j++) {
            float2 f0 = __half22float2(*(const __half2*)&cur[j].x);
            float2 f1 = __half22float2(*(const __half2*)&cur[j].y);
            float2 f2 = __half22float2(*(const __half2*)&cur[j].z);
            float2 f3 = __half22float2(*(const __half2*)&cur[j].w);
            u[8 * j + 0] = f0.x; u[8 * j + 1] = f0.y;
            u[8 * j + 2] = f1.x; u[8 * j + 3] = f1.y;
            u[8 * j + 4] = f2.x; u[8 * j + 5] = f2.y;
            u[8 * j + 6] = f3.x; u[8 * j + 7] = f3.y;
        }

        // bb[o] = sum_d vs[d]*u[d]  (4 independent FMA chains)
        float d0 = 0.f, d1 = 0.f, d2 = 0.f, d3 = 0.f;
        #pragma unroll
        for (int j = 0; j < 8; j++) {
            d0 = fmaf(vs[4 * j + 0], u[4 * j + 0], d0);
            d1 = fmaf(vs[4 * j + 1], u[4 * j + 1], d1);
            d2 = fmaf(vs[4 * j + 2], u[4 * j + 2], d2);
            d3 = fmaf(vs[4 * j + 3], u[4 * j + 3], d3);
        }
        float bb = (d0 + d1) + (d2 + d3);

        // softmax over the 32 lanes (= 32 output capsules)
        float m = bb;
        #pragma unroll
        for (int s = 16; s > 0; s >>= 1)
            m = fmaxf(m, __shfl_xor_sync(0xffffffffu, m, s));
        float ex = expf(bb - m);
        float sum = ex;
        #pragma unroll
        for (int s = 16; s > 0; s >>= 1)
            sum += __shfl_xor_sync(0xffffffffu, sum, s);
        float c = ex / sum;

        #pragma unroll
        for (int d = 0; d < 32; d++)
            sacc[d] = fmaf(c, u[d], sacc[d]);

        #pragma unroll
        for (int j = 0; j < 4; j++) cur[j] = nxt[j];
    }

    // block reduce the 8 warps' register partials (pitch 33 -> conflict-free)
    float* rp = red + (w * 32 + o) * 33;
    #pragma unroll
    for (int d = 0; d < 32; d++) rp[d] = sacc[d];
    __syncthreads();

    const int od0 = threadIdx.x * 4;
    float r[4] = {0.f, 0.f, 0.f, 0.f};
    #pragma unroll
    for (int w2 = 0; w2 < 8; w2++) {
        #pragma unroll
        for (int q = 0; q < 4; q++) {
            int od = od0 + q;
            r[q] += red[(w2 * 32 + (od >> 5)) * 33 + (od & 31)];
        }
    }
    *(float4*)&g_spart[((size_t)blockIdx.x) * OD + od0] =
        make_float4(r[0], r[1], r[2], r[3]);
}

// ---------------------------------------------------------------------------
// Reduce the 8 deterministic partials, squash, update vsum (or emit output).
__global__ __launch_bounds__(256) void k_squash(float* __restrict__ out, int final_) {
    const int g    = blockIdx.x * 8 + (threadIdx.x >> 5);
    const int lane = threadIdx.x & 31;
    const int b    = g >> 5;
    const int o    = g & 31;

    float val = 0.f;
    #pragma unroll
    for (int j = 0; j < 8; j++)
        val += g_spart[((size_t)(b * 8 + j)) * OD + o * 32 + lane];

    float sq = val * val;
    #pragma unroll
    for (int s = 16; s > 0; s >>= 1)
        sq += __shfl_xor_sync(0xffffffffu, sq, s);

    float scale = sq / (1.f + sq) / sqrtf(sq + EPSQ);
    float v = val * scale;

    if (final_)
        out[((size_t)b * 32 + o) * 32 + lane] = v;
    else
        g_vsum[b * OD + o * 32 + lane] += v;
}

// ---------------------------------------------------------------------------
extern "C" void kernel_launch(void* const* d_in, const int* in_sizes, int n_in,
                              void* d_out, int out_size) {
    const float* x = (const float*)d_in[0];   // [64, 2048, 16]
    const float* W = (const float*)d_in[1];   // [32, 2048, 32, 16]
    float* out = (float*)d_out;               // [64, 32, 32]

    k_zero_vsum<<<64, 256>>>();
    k_transform<<<dim3(NI, 2), 128>>>(x, W);

    // iteration 0: uniform coupling (softmax of zeros) -> plain mean
    k_sum0<<<B_ * 8, 256>>>();
    k_squash<<<256, 256>>>(out, 0);

    // iterations 1,2
    k_route<<<B_ * 8, 256>>>();
    k_squash<<<256, 256>>>(out, 0);
    k_route<<<B_ * 8, 256>>>();
    k_squash<<<256, 256>>>(out, 1);
}